// round 7
// baseline (speedup 1.0000x reference)
#include <cuda_runtime.h>

// Micromagnetic LLG RK4 solver — persistent kernel, halo stepping.
// Round 7: OCCUPANCY + PARALLEL-ARRIVE BARRIER.
// 64 CTAs x 1024 threads (32 warps/SM, 2x latency hiding). CTA r owns global
// rows 4r..4r+3; window = 12 rows (4-row halo each side). Thread
// (ty = tid>>8 in 0..3, c = tid&255) handles window rows L = 4k+ty (k=0..2)
// — perfectly balanced: 7 row-computes per thread per RK4 step, own row at
// k==1 (L = 4+ty). All N/S neighbors via double-buffered smem rows (proven
// R3/R5 pattern); W/E via smem halo columns. One grid barrier per RK4 step.
// Barrier v3: arrive = return-less atomicAdd (RED, parallel); CTA0 polls the
// counter, resets it, bumps generation; others spin on generation.

#define NXg 256
#define NYg 256
#define PLANE (NXg * NYg)
#define TSTEPS 256
#define NSIG 2
#define NSRC 3
#define NPROBE 5
#define RELAXN 100
#define NBLK 64
#define NT 1024
#define NROWS 12
#define SROW 258
#define SMEM_BYTES (2 * NROWS * SROW * 16)

__device__ float4 g_m4[PLANE];
__device__ unsigned g_cnt = 0;           // arrive counter (reset each barrier)
__device__ volatile unsigned g_gen = 0;  // generation (release flag)

// Parallel-arrive central barrier. Arrivals are RED (atomicAdd, result
// unused) -> no serialization. CTA0 waits for all 64, resets the counter,
// fences, bumps the generation; everyone else spins on the generation.
// Counter is 0 at the start of every run (reset before each release).
__device__ __forceinline__ void gridbar() {
    __syncthreads();
    if (threadIdx.x == 0) {
        __threadfence();
        unsigned gen = g_gen;            // read BEFORE arriving
        atomicAdd(&g_cnt, 1u);           // return unused -> RED
        if (blockIdx.x == 0) {
            while (*(volatile unsigned*)&g_cnt < NBLK) { }
            g_cnt = 0;
            __threadfence();             // reset visible before release
            g_gen = gen + 1u;
        } else {
            while (g_gen == gen) { }
        }
        __threadfence();
    }
    __syncthreads();
}

__device__ __forceinline__ float3 lap_torque(
    float ux, float uy, float uz,
    float sx, float sy, float sz,          // N+S+W+E sums
    float bx, float by, float bz_, float bzAdd,
    float CEx, float CD, float alpha, float inv)
{
    float lx = sx - 4.0f * ux, ly = sy - 4.0f * uy, lz = sz - 4.0f * uz;
    float Bx = bx + CEx * lx;
    float By = by + CEx * ly;
    float Bz = bz_ + bzAdd + CEx * lz - CD * uz;
    float c1x = uy * Bz - uz * By;
    float c1y = uz * Bx - ux * Bz;
    float c1z = ux * By - uy * Bx;
    float c2x = uy * c1z - uz * c1y;
    float c2y = uz * c1x - ux * c1z;
    float c2z = ux * c1y - uy * c1x;
    const float CS = 1.0e-4f;
    float3 t;
    t.x = -inv * (c1x + alpha * c2x) + CS * (ux * uy);
    t.y = -inv * (c1y + alpha * c2y) + CS * (-(uz * uz + ux * ux));
    t.z = -inv * (c1z + alpha * c2z) + CS * (uy * uz);
    return t;
}

#define U(b, L) (smf4 + ((b) * NROWS + (L)) * SROW)

// One RK4 stage: rows L = 4k+ty valid iff L in [s, 11-s] (warp-uniform).
// Stage-s valid set exactly covers the neighbors needed by stage s+1.
#define STAGE(s, ib, ob, coefE, wK, LAST)                                      \
  {                                                                            \
    _Pragma("unroll")                                                          \
    for (int k = 0; k < 3; k++) {                                              \
      int L = 4 * k + ty;                                                      \
      if (L >= (s) && L <= 11 - (s)) {                                         \
        float4 nN = U(ib, L - 1)[c + 1];                                       \
        float4 nS = U(ib, L + 1)[c + 1];                                       \
        float4 nW = U(ib, L)[c];                                               \
        float4 nE = U(ib, L)[c + 2];                                           \
        float3 kv = lap_torque(ux[k], uy[k], uz[k],                            \
            nN.x + nS.x + nW.x + nE.x,                                         \
            nN.y + nS.y + nW.y + nE.y,                                         \
            nN.z + nS.z + nW.z + nE.z,                                         \
            bxr[k], byr[k], bzr[k], bzadd[k], CEx, CD, alpha, inv);            \
        if (k == 1) { ax += (wK) * kv.x; ay += (wK) * kv.y;                    \
                      az += (wK) * kv.z; }                                     \
        if (!(LAST)) {                                                         \
          float nx2 = mxr[k] + (coefE) * kv.x;                                 \
          float ny2 = myr[k] + (coefE) * kv.y;                                 \
          float nz2 = mzr[k] + (coefE) * kv.z;                                 \
          ux[k] = nx2; uy[k] = ny2; uz[k] = nz2;                               \
          float4 ov = make_float4(nx2, ny2, nz2, 0.0f);                        \
          U(ob, L)[c + 1] = ov;                                                \
          if (c == 0)   U(ob, L)[0]   = ov;                                    \
          if (c == 255) U(ob, L)[257] = ov;                                    \
        }                                                                      \
      }                                                                        \
    }                                                                          \
    if (!(LAST)) __syncthreads();                                              \
  }

#define RK4STEP()                                                              \
  { float ax = 0.0f, ay = 0.0f, az = 0.0f;                                     \
    STAGE(1, 0, 1, h2, 1.0f, false)                                            \
    STAGE(2, 1, 0, h2, 2.0f, false)                                            \
    STAGE(3, 0, 1, hh, 2.0f, false)                                            \
    STAGE(4, 1, 0, 0.0f, 1.0f, true)                                           \
    mxr[1] += h6 * ax; myr[1] += h6 * ay; mzr[1] += h6 * az; }

// Refresh window after the barrier: halo rows (k=0,2) from global, own row
// (k=1) from registers. Repopulate smem buffer 0 for the next stage 1.
#define RELOAD()                                                               \
  { _Pragma("unroll")                                                          \
    for (int k = 0; k < 3; k++) {                                              \
      int L = 4 * k + ty;                                                      \
      float4 v;                                                                \
      if (k == 1) v = make_float4(mxr[1], myr[1], mzr[1], 0.0f);               \
      else        v = __ldcg(&g_m4[growr[k] * NYg + c]);                       \
      mxr[k] = v.x; myr[k] = v.y; mzr[k] = v.z;                                \
      ux[k] = v.x; uy[k] = v.y; uz[k] = v.z;                                   \
      U(0, L)[c + 1] = v;                                                      \
      if (c == 0)   U(0, L)[0]   = v;                                          \
      if (c == 255) U(0, L)[257] = v;                                          \
    }                                                                          \
    __syncthreads(); }

__global__ void __launch_bounds__(NT, 1)
mm_kernel(const float* __restrict__ sig, const float* __restrict__ Bext,
          const float* __restrict__ MsatP, const int* __restrict__ srcP,
          const int* __restrict__ probeP, const int* __restrict__ finalP,
          float* __restrict__ out)
{
    extern __shared__ float4 smf4[];

    const int tid  = threadIdx.x;
    const int c    = tid & 255;
    const int ty   = tid >> 8;             // 0..3, warp-uniform
    const int r    = blockIdx.x;
    const int gown = 4 * r + ty;           // owned global row (window L=4+ty)

    const float Msat = *MsatP;
    const float CEx = (float)(2.0 * 3.5e-12 / ((double)Msat * (5e-8 * 5e-8)));
    const float CD  = (float)(4e-7 * 3.14159265358979323846 * (double)Msat);
    const float hh  = (float)(175950000000.0 * 5e-12);   // GAMMA_LL * DT
    const float h2  = 0.5f * hh;
    const float h6  = hh * (1.0f / 6.0f);
    const int final_board = *finalP;

    // Window row L = 4k+ty -> global grow[k] = clamp(4r - 4 + L).
    int growr[3];
    #pragma unroll
    for (int k = 0; k < 3; k++) {
        int g = 4 * r - 4 + 4 * k + ty;
        growr[k] = g < 0 ? 0 : (g > NXg - 1 ? NXg - 1 : g);
    }

    // B_ext per handled row -> registers.
    float bxr[3], byr[3], bzr[3];
    #pragma unroll
    for (int k = 0; k < 3; k++) {
        int gi = growr[k] * NYg + c;
        bxr[k] = __ldg(Bext + 0 * PLANE + gi);
        byr[k] = __ldg(Bext + 1 * PLANE + gi);
        bzr[k] = __ldg(Bext + 2 * PLANE + gi);
    }

    // Source-id per handled row.
    int sid[3];
    {
        int s0r = srcP[0], s0c = srcP[1];
        int s1r = srcP[2], s1c = srcP[3];
        int s2r = srcP[4], s2c = srcP[5];
        #pragma unroll
        for (int k = 0; k < 3; k++) {
            int g = growr[k];
            sid[k] = (g == s0r && c == s0c) ? 0 :
                     (g == s1r && c == s1c) ? 1 :
                     (g == s2r && c == s2c) ? 2 : -1;
        }
    }
    // Probe-id at owned cell.
    int pid = -1;
    #pragma unroll
    for (int k = 0; k < NPROBE; k++)
        if (probeP[2 * k] == gown && probeP[2 * k + 1] == c) pid = k;

    float ux[3], uy[3], uz[3];           // stage-input values
    float mxr[3], myr[3], mzr[3];        // base m for this step
    float bzadd[3];
    #pragma unroll
    for (int k = 0; k < 3; k++) bzadd[k] = 0.0f;

    // ---- init: m0 = (0,1,0) everywhere ----
    #pragma unroll
    for (int k = 0; k < 3; k++) {
        int L = 4 * k + ty;
        mxr[k] = 0.0f; myr[k] = 1.0f; mzr[k] = 0.0f;
        ux[k] = 0.0f;  uy[k] = 1.0f;  uz[k] = 0.0f;
        float4 v = make_float4(0.0f, 1.0f, 0.0f, 0.0f);
        U(0, L)[c + 1] = v;
        if (c == 0)   U(0, L)[0]   = v;
        if (c == 255) U(0, L)[257] = v;
    }
    __syncthreads();

    // ---- relax phase: alpha = 0.5 ----
    {
        const float alpha = 0.5f;
        const float inv = 1.0f / (1.0f + alpha * alpha);
        for (int s = 0; s < RELAXN; s++) {
            RK4STEP();
            __stcg(&g_m4[gown * NYg + c],
                   make_float4(mxr[1], myr[1], mzr[1], 0.0f));
            gridbar();
            RELOAD();
        }
    }
    const float mrx = mxr[1], mry = myr[1], mrz = mzr[1];   // m_relaxed

    // ---- driven phase: alpha = 0.01 ----
    {
        const float alpha = 0.01f;
        const float inv = 1.0f / (1.0f + alpha * alpha);
        for (int sgn = 0; sgn < NSIG; sgn++) {
            if (sgn > 0) {   // reset to m_relaxed
                mxr[1] = mrx; myr[1] = mry; mzr[1] = mrz;
                __stcg(&g_m4[gown * NYg + c], make_float4(mrx, mry, mrz, 0.0f));
                gridbar();
                RELOAD();
            }
            for (int t = 0; t < TSTEPS; t++) {
                const float* sp = sig + (sgn * TSTEPS + t) * NSRC;
                float sv0 = __ldg(sp + 0), sv1 = __ldg(sp + 1), sv2 = __ldg(sp + 2);
                #pragma unroll
                for (int k = 0; k < 3; k++)
                    bzadd[k] = (sid[k] == 0) ? sv0 :
                               (sid[k] == 1) ? sv1 :
                               (sid[k] == 2) ? sv2 : 0.0f;
                RK4STEP();
                __stcg(&g_m4[gown * NYg + c],
                       make_float4(mxr[1], myr[1], mzr[1], 0.0f));
                if (pid >= 0) {
                    float val = final_board ? (mzr[1] - mrz) * Msat : mzr[1];
                    out[(sgn * TSTEPS + t) * NPROBE + pid] = val;
                }
                gridbar();
                RELOAD();
            }
        }
    }
}

extern "C" void kernel_launch(void* const* d_in, const int* in_sizes, int n_in,
                              void* d_out, int out_size) {
    const float* sig    = (const float*)d_in[0];  // (2, 256, 3)
    const float* Bext   = (const float*)d_in[1];  // (1, 3, 256, 256)
    const float* MsatP  = (const float*)d_in[2];  // scalar
    const int*   srcP   = (const int*)d_in[3];    // (3, 2)
    const int*   probeP = (const int*)d_in[4];    // (5, 2)
    const int*   finalP = (const int*)d_in[5];    // scalar
    float* out = (float*)d_out;                   // (2, 256, 5)
    (void)in_sizes; (void)n_in; (void)out_size;

    cudaFuncSetAttribute(mm_kernel,
                         cudaFuncAttributeMaxDynamicSharedMemorySize,
                         SMEM_BYTES);
    mm_kernel<<<NBLK, NT, SMEM_BYTES>>>(sig, Bext, MsatP, srcP, probeP,
                                        finalP, out);
}

// round 8
// speedup vs baseline: 1.0598x; 1.0598x over previous
#include <cuda_runtime.h>

// Micromagnetic LLG RK4 solver — persistent kernel, halo stepping.
// Round 8: 128 CTAs x 1024 threads — ALL 128 SMs busy AND 32 warps/SM.
// CTA r owns global rows {2r, 2r+1}; window = 10 rows (4-row halo each
// side), same footprint as the best (R6) kernel. Four thread-layers
// (ty = tid>>8 in 0..3, c = tid&255): thread handles window rows
// L = ty + 4k (k=0..2). Per RK4 stage, row L is valid iff L in [s, 9-s];
// this gives EVERY thread exactly 5 row-computes per step (vs 10 in R6)
// with warp-uniform predicates. Only layers ty<2 own a real row (window
// row 4+ty = global 2r+ty); they write global state and probes.
// Grid barrier: two-level tree (proven R5) — 16-way group atomicInc,
// 8 concurrent groups, top-level 8-way, generation release.

#define NXg 256
#define NYg 256
#define PLANE (NXg * NYg)
#define TSTEPS 256
#define NSIG 2
#define NSRC 3
#define NPROBE 5
#define RELAXN 100
#define NBLK 128
#define NT 1024
#define NROWS 10
#define SROW 258
#define SMEM_BYTES (2 * NROWS * SROW * 16)

__device__ float4 g_m4[PLANE];
__device__ unsigned g_cnt0[8 * 64];      // 8 group counters, 256B apart
__device__ unsigned g_cnt1 = 0;          // top-level counter (8 groups)
__device__ volatile unsigned g_gen = 0;  // generation (release flag)

// Two-level tree barrier (proven round 5).
__device__ __forceinline__ void gridbar(int r) {
    __syncthreads();
    if (threadIdx.x == 0) {
        __threadfence();
        unsigned gen = g_gen;
        unsigned grp = ((unsigned)r >> 4) << 6;
        if (atomicInc(&g_cnt0[grp], 15u) == 15u) {
            if (atomicInc(&g_cnt1, 7u) == 7u) {
                g_gen = gen + 1u;
            } else {
                while (g_gen == gen) { }
            }
        } else {
            while (g_gen == gen) { }
        }
        __threadfence();
    }
    __syncthreads();
}

__device__ __forceinline__ float3 lap_torque(
    float ux, float uy, float uz,
    float sx, float sy, float sz,          // N+S+W+E sums
    float bx, float by, float bz_, float bzAdd,
    float CEx, float CD, float alpha, float inv)
{
    float lx = sx - 4.0f * ux, ly = sy - 4.0f * uy, lz = sz - 4.0f * uz;
    float Bx = bx + CEx * lx;
    float By = by + CEx * ly;
    float Bz = bz_ + bzAdd + CEx * lz - CD * uz;
    float c1x = uy * Bz - uz * By;
    float c1y = uz * Bx - ux * Bz;
    float c1z = ux * By - uy * Bx;
    float c2x = uy * c1z - uz * c1y;
    float c2y = uz * c1x - ux * c1z;
    float c2z = ux * c1y - uy * c1x;
    const float CS = 1.0e-4f;
    float3 t;
    t.x = -inv * (c1x + alpha * c2x) + CS * (ux * uy);
    t.y = -inv * (c1y + alpha * c2y) + CS * (-(uz * uz + ux * ux));
    t.z = -inv * (c1z + alpha * c2z) + CS * (uy * uz);
    return t;
}

#define U(b, L) (smf4 + ((b) * NROWS + (L)) * SROW)

// One RK4 stage. Rows L = ty + 4k, valid iff L in [s, 9-s] (warp-uniform).
// Own row contributes to the RK4 accumulator when own && k == 1.
#define STAGE(s, ib, ob, coefE, wK, LAST)                                      \
  {                                                                            \
    _Pragma("unroll")                                                          \
    for (int k = 0; k < 3; k++) {                                              \
      int L = ty + 4 * k;                                                      \
      if (L >= (s) && L <= 9 - (s)) {                                          \
        float4 nN = U(ib, L - 1)[c + 1];                                       \
        float4 nS = U(ib, L + 1)[c + 1];                                       \
        float4 nW = U(ib, L)[c];                                               \
        float4 nE = U(ib, L)[c + 2];                                           \
        float3 kv = lap_torque(ux[k], uy[k], uz[k],                            \
            nN.x + nS.x + nW.x + nE.x,                                         \
            nN.y + nS.y + nW.y + nE.y,                                         \
            nN.z + nS.z + nW.z + nE.z,                                         \
            bxr[k], byr[k], bzr[k], bzadd[k], CEx, CD, alpha, inv);            \
        if (own && k == 1) { ax += (wK) * kv.x; ay += (wK) * kv.y;             \
                             az += (wK) * kv.z; }                              \
        if (!(LAST)) {                                                         \
          float nx2 = mxr[k] + (coefE) * kv.x;                                 \
          float ny2 = myr[k] + (coefE) * kv.y;                                 \
          float nz2 = mzr[k] + (coefE) * kv.z;                                 \
          ux[k] = nx2; uy[k] = ny2; uz[k] = nz2;                               \
          float4 ov = make_float4(nx2, ny2, nz2, 0.0f);                        \
          U(ob, L)[c + 1] = ov;                                                \
          if (c == 0)   U(ob, L)[0]   = ov;                                    \
          if (c == 255) U(ob, L)[257] = ov;                                    \
        }                                                                      \
      }                                                                        \
    }                                                                          \
    if (!(LAST)) __syncthreads();                                              \
  }

#define RK4STEP()                                                              \
  { float ax = 0.0f, ay = 0.0f, az = 0.0f;                                     \
    STAGE(1, 0, 1, h2, 1.0f, false)                                            \
    STAGE(2, 1, 0, h2, 2.0f, false)                                            \
    STAGE(3, 0, 1, hh, 2.0f, false)                                            \
    STAGE(4, 1, 0, 0.0f, 1.0f, true)                                           \
    if (own) { mxr[1] += h6 * ax; myr[1] += h6 * ay; mzr[1] += h6 * az; } }

// Refresh window after the barrier: own row (own && k==1) from registers,
// all other handled rows from global. Repopulate smem buffer 0.
#define RELOAD()                                                               \
  { _Pragma("unroll")                                                          \
    for (int k = 0; k < 3; k++) {                                              \
      int L = ty + 4 * k;                                                      \
      if (L <= 9) {                                                            \
        float4 v;                                                              \
        if (own && k == 1) v = make_float4(mxr[1], myr[1], mzr[1], 0.0f);      \
        else               v = __ldcg(&g_m4[growr[k] * NYg + c]);              \
        mxr[k] = v.x; myr[k] = v.y; mzr[k] = v.z;                              \
        ux[k] = v.x; uy[k] = v.y; uz[k] = v.z;                                 \
        U(0, L)[c + 1] = v;                                                    \
        if (c == 0)   U(0, L)[0]   = v;                                        \
        if (c == 255) U(0, L)[257] = v;                                        \
      }                                                                        \
    }                                                                          \
    __syncthreads(); }

__global__ void __launch_bounds__(NT, 1)
mm_kernel(const float* __restrict__ sig, const float* __restrict__ Bext,
          const float* __restrict__ MsatP, const int* __restrict__ srcP,
          const int* __restrict__ probeP, const int* __restrict__ finalP,
          float* __restrict__ out)
{
    extern __shared__ float4 smf4[];

    const int tid  = threadIdx.x;
    const int c    = tid & 255;
    const int ty   = tid >> 8;              // 0..3, warp-uniform
    const int r    = blockIdx.x;
    const bool own = (ty < 2);              // layers 0/1 own a real row
    const int gown = 2 * r + ty;            // global row when own

    const float Msat = *MsatP;
    const float CEx = (float)(2.0 * 3.5e-12 / ((double)Msat * (5e-8 * 5e-8)));
    const float CD  = (float)(4e-7 * 3.14159265358979323846 * (double)Msat);
    const float hh  = (float)(175950000000.0 * 5e-12);   // GAMMA_LL * DT
    const float h2  = 0.5f * hh;
    const float h6  = hh * (1.0f / 6.0f);
    const int final_board = *finalP;

    // Window row L = ty + 4k -> global grow[k] = clamp(2r - 4 + L).
    int growr[3];
    #pragma unroll
    for (int k = 0; k < 3; k++) {
        int g = 2 * r - 4 + ty + 4 * k;
        growr[k] = g < 0 ? 0 : (g > NXg - 1 ? NXg - 1 : g);
    }

    // B_ext per handled row -> registers.
    float bxr[3], byr[3], bzr[3];
    #pragma unroll
    for (int k = 0; k < 3; k++) {
        int gi = growr[k] * NYg + c;
        bxr[k] = __ldg(Bext + 0 * PLANE + gi);
        byr[k] = __ldg(Bext + 1 * PLANE + gi);
        bzr[k] = __ldg(Bext + 2 * PLANE + gi);
    }

    // Source-id per handled row.
    int sid[3];
    {
        int s0r = srcP[0], s0c = srcP[1];
        int s1r = srcP[2], s1c = srcP[3];
        int s2r = srcP[4], s2c = srcP[5];
        #pragma unroll
        for (int k = 0; k < 3; k++) {
            int g = growr[k];
            sid[k] = (g == s0r && c == s0c) ? 0 :
                     (g == s1r && c == s1c) ? 1 :
                     (g == s2r && c == s2c) ? 2 : -1;
        }
    }
    // Probe-id at owned cell.
    int pid = -1;
    if (own) {
        #pragma unroll
        for (int k = 0; k < NPROBE; k++)
            if (probeP[2 * k] == gown && probeP[2 * k + 1] == c) pid = k;
    }

    float ux[3], uy[3], uz[3];           // stage-input values
    float mxr[3], myr[3], mzr[3];        // base m for this step
    float bzadd[3];
    #pragma unroll
    for (int k = 0; k < 3; k++) bzadd[k] = 0.0f;

    // ---- init: m0 = (0,1,0) everywhere ----
    #pragma unroll
    for (int k = 0; k < 3; k++) {
        int L = ty + 4 * k;
        mxr[k] = 0.0f; myr[k] = 1.0f; mzr[k] = 0.0f;
        ux[k] = 0.0f;  uy[k] = 1.0f;  uz[k] = 0.0f;
        if (L <= 9) {
            float4 v = make_float4(0.0f, 1.0f, 0.0f, 0.0f);
            U(0, L)[c + 1] = v;
            if (c == 0)   U(0, L)[0]   = v;
            if (c == 255) U(0, L)[257] = v;
        }
    }
    __syncthreads();

    // ---- relax phase: alpha = 0.5 ----
    {
        const float alpha = 0.5f;
        const float inv = 1.0f / (1.0f + alpha * alpha);
        for (int s = 0; s < RELAXN; s++) {
            RK4STEP();
            if (own)
                __stcg(&g_m4[gown * NYg + c],
                       make_float4(mxr[1], myr[1], mzr[1], 0.0f));
            gridbar(r);
            RELOAD();
        }
    }
    const float mrx = mxr[1], mry = myr[1], mrz = mzr[1];   // m_relaxed (own)

    // ---- driven phase: alpha = 0.01 ----
    {
        const float alpha = 0.01f;
        const float inv = 1.0f / (1.0f + alpha * alpha);
        for (int sgn = 0; sgn < NSIG; sgn++) {
            if (sgn > 0) {   // reset to m_relaxed
                if (own) {
                    mxr[1] = mrx; myr[1] = mry; mzr[1] = mrz;
                    __stcg(&g_m4[gown * NYg + c],
                           make_float4(mrx, mry, mrz, 0.0f));
                }
                gridbar(r);
                RELOAD();
            }
            for (int t = 0; t < TSTEPS; t++) {
                const float* sp = sig + (sgn * TSTEPS + t) * NSRC;
                float sv0 = __ldg(sp + 0), sv1 = __ldg(sp + 1), sv2 = __ldg(sp + 2);
                #pragma unroll
                for (int k = 0; k < 3; k++)
                    bzadd[k] = (sid[k] == 0) ? sv0 :
                               (sid[k] == 1) ? sv1 :
                               (sid[k] == 2) ? sv2 : 0.0f;
                RK4STEP();
                if (own)
                    __stcg(&g_m4[gown * NYg + c],
                           make_float4(mxr[1], myr[1], mzr[1], 0.0f));
                if (pid >= 0) {
                    float val = final_board ? (mzr[1] - mrz) * Msat : mzr[1];
                    out[(sgn * TSTEPS + t) * NPROBE + pid] = val;
                }
                gridbar(r);
                RELOAD();
            }
        }
    }
}

extern "C" void kernel_launch(void* const* d_in, const int* in_sizes, int n_in,
                              void* d_out, int out_size) {
    const float* sig    = (const float*)d_in[0];  // (2, 256, 3)
    const float* Bext   = (const float*)d_in[1];  // (1, 3, 256, 256)
    const float* MsatP  = (const float*)d_in[2];  // scalar
    const int*   srcP   = (const int*)d_in[3];    // (3, 2)
    const int*   probeP = (const int*)d_in[4];    // (5, 2)
    const int*   finalP = (const int*)d_in[5];    // scalar
    float* out = (float*)d_out;                   // (2, 256, 5)
    (void)in_sizes; (void)n_in; (void)out_size;

    cudaFuncSetAttribute(mm_kernel,
                         cudaFuncAttributeMaxDynamicSharedMemorySize,
                         SMEM_BYTES);
    mm_kernel<<<NBLK, NT, SMEM_BYTES>>>(sig, Bext, MsatP, srcP, probeP,
                                        finalP, out);
}

// round 9
// speedup vs baseline: 1.4135x; 1.3338x over previous
#include <cuda_runtime.h>

// Micromagnetic LLG RK4 solver — persistent kernel, halo stepping (R6
// compute path), Round 9: NEIGHBOR-ONLY per-step sync with double-buffered
// global state.
// 128 CTAs x 512 threads; CTA r owns global rows {2r, 2r+1}; 10-row window
// (4-row halo each side); 4 RK4 stages computed locally per step; ONE sync
// per step. Step n writes g_mbuf[n&1]; CTA r's halo depends only on CTAs
// r-2..r+2, so sync = publish own monotonic flag (fence + st.cg) + poll the
// 4 neighbor flags (thread 0, 4 pipelined scalar ld.cg). Chip runs as a
// skew-tolerant wavefront; no global straggler coupling.
// Safety: publish-before-wait => min-flag CTA always proceeds (no deadlock);
// flag >= n-1 from a neighbor implies its reads of the buffer I overwrite
// are done (no WAR); flags monotonic + equal at run end => replay-safe.

#define NXg 256
#define NYg 256
#define PLANE (NXg * NYg)
#define TSTEPS 256
#define NSIG 2
#define NSRC 3
#define NPROBE 5
#define RELAXN 100
#define NBLK 128
#define NT 512
#define NROWS 10
#define SROW 258
#define SMEM_BYTES (2 * NROWS * SROW * 16)

__device__ float4 g_mbuf[2][PLANE];
__device__ unsigned g_flag[NBLK * 8];    // zero-init; one flag per 32B sector

// Publish own flag (release) then wait for the 4 dependency CTAs to reach
// the same level. Executed by thread 0; CTA-wide ordering via syncthreads.
#define NBRSYNC()                                                              \
  { seq++;                                                                     \
    const unsigned tgt = fbase + seq;                                          \
    __syncthreads();                                                           \
    if (threadIdx.x == 0) {                                                    \
        __threadfence();                                                       \
        asm volatile("st.global.cg.u32 [%0], %1;"                              \
                     :: "l"(g_flag + 8 * r), "r"(tgt) : "memory");             \
        unsigned fa, fb, fc, fd;                                               \
        do {                                                                   \
            asm volatile("ld.global.cg.u32 %0, [%1];"                          \
                         : "=r"(fa) : "l"(g_flag + fn0) : "memory");           \
            asm volatile("ld.global.cg.u32 %0, [%1];"                          \
                         : "=r"(fb) : "l"(g_flag + fn1) : "memory");           \
            asm volatile("ld.global.cg.u32 %0, [%1];"                          \
                         : "=r"(fc) : "l"(g_flag + fn2) : "memory");           \
            asm volatile("ld.global.cg.u32 %0, [%1];"                          \
                         : "=r"(fd) : "l"(g_flag + fn3) : "memory");           \
        } while (((int)(fa - tgt) | (int)(fb - tgt) |                          \
                  (int)(fc - tgt) | (int)(fd - tgt)) < 0);                     \
        __threadfence();                                                       \
    }                                                                          \
    __syncthreads(); }

__device__ __forceinline__ float3 lap_torque(
    float ux, float uy, float uz,
    float sx, float sy, float sz,          // N+S+W+E sums
    float bx, float by, float bz_, float bzAdd,
    float CEx, float CD, float alpha, float inv)
{
    float lx = sx - 4.0f * ux, ly = sy - 4.0f * uy, lz = sz - 4.0f * uz;
    float Bx = bx + CEx * lx;
    float By = by + CEx * ly;
    float Bz = bz_ + bzAdd + CEx * lz - CD * uz;
    float c1x = uy * Bz - uz * By;
    float c1y = uz * Bx - ux * Bz;
    float c1z = ux * By - uy * Bx;
    float c2x = uy * c1z - uz * c1y;
    float c2y = uz * c1x - ux * c1z;
    float c2z = ux * c1y - uy * c1x;
    const float CS = 1.0e-4f;
    float3 t;
    t.x = -inv * (c1x + alpha * c2x) + CS * (ux * uy);
    t.y = -inv * (c1y + alpha * c2y) + CS * (-(uz * uz + ux * ux));
    t.z = -inv * (c1z + alpha * c2z) + CS * (uy * uz);
    return t;
}

#define U(b, L) (smf4 + ((b) * NROWS + (L)) * SROW)

// One RK4 stage (R6 strip mapping): ty0 computes k>=s, ty1 k<=4-s.
#define STAGE(s, ib, ob, coefE, wK, LAST)                                      \
  {                                                                            \
    float4 bnd = U(ib, bndL)[c + 1];                                           \
    _Pragma("unroll")                                                          \
    for (int k = 0; k < 5; k++) {                                              \
      bool valid = ty ? (k <= 4 - (s)) : (k >= (s));                           \
      if (valid) {                                                             \
        int L = lbase + k;                                                     \
        float nNx = (k > 0) ? ux[k - 1] : bnd.x;                               \
        float nNy = (k > 0) ? uy[k - 1] : bnd.y;                               \
        float nNz = (k > 0) ? uz[k - 1] : bnd.z;                               \
        float nSx = (k < 4) ? ux[k + 1] : bnd.x;                               \
        float nSy = (k < 4) ? uy[k + 1] : bnd.y;                               \
        float nSz = (k < 4) ? uz[k + 1] : bnd.z;                               \
        float4 nW = U(ib, L)[c];                                               \
        float4 nE = U(ib, L)[c + 2];                                           \
        float3 kv = lap_torque(ux[k], uy[k], uz[k],                            \
            nNx + nSx + nW.x + nE.x,                                           \
            nNy + nSy + nW.y + nE.y,                                           \
            nNz + nSz + nW.z + nE.z,                                           \
            bxr[k], byr[k], bzr[k], bzadd[k], CEx, CD, alpha, inv);            \
        if (k == kown) { ax += (wK) * kv.x; ay += (wK) * kv.y;                 \
                         az += (wK) * kv.z; }                                  \
        if (!(LAST)) {                                                         \
          float nx2 = mxr[k] + (coefE) * kv.x;                                 \
          float ny2 = myr[k] + (coefE) * kv.y;                                 \
          float nz2 = mzr[k] + (coefE) * kv.z;                                 \
          vx[k] = nx2; vy[k] = ny2; vz[k] = nz2;                               \
          float4 ov = make_float4(nx2, ny2, nz2, 0.0f);                        \
          U(ob, L)[c + 1] = ov;                                                \
          if (c == 0)   U(ob, L)[0]   = ov;                                    \
          if (c == 255) U(ob, L)[257] = ov;                                    \
        }                                                                      \
      }                                                                        \
    }                                                                          \
    _Pragma("unroll")                                                          \
    for (int k = 0; k < 5; k++) { ux[k] = vx[k]; uy[k] = vy[k];                \
                                  uz[k] = vz[k]; }                             \
    __syncthreads();                                                           \
  }

#define RK4STEP()                                                              \
  { float ax = 0.0f, ay = 0.0f, az = 0.0f;                                     \
    STAGE(1, 0, 1, h2, 1.0f, false)                                            \
    STAGE(2, 1, 0, h2, 2.0f, false)                                            \
    STAGE(3, 0, 1, hh, 2.0f, false)                                            \
    STAGE(4, 1, 0, 0.0f, 1.0f, true)                                           \
    mxr[kown] += h6 * ax; myr[kown] += h6 * ay; mzr[kown] += h6 * az; }

// Refresh strip from buffer `gb` after a sync: halo rows from global, own
// row from registers. Repopulate smem buffer 0 for the next stage 1.
#define RELOAD(gb)                                                             \
  { _Pragma("unroll")                                                          \
    for (int k = 0; k < 5; k++) {                                              \
      int L = lbase + k;                                                       \
      float4 v;                                                                \
      if (k == kown) v = make_float4(mxr[k], myr[k], mzr[k], 0.0f);            \
      else           v = __ldcg(&(gb)[growr[k] * NYg + c]);                    \
      mxr[k] = v.x; myr[k] = v.y; mzr[k] = v.z;                                \
      ux[k] = v.x; uy[k] = v.y; uz[k] = v.z;                                   \
      vx[k] = v.x; vy[k] = v.y; vz[k] = v.z;                                   \
      U(0, L)[c + 1] = v;                                                      \
      if (c == 0)   U(0, L)[0]   = v;                                          \
      if (c == 255) U(0, L)[257] = v;                                          \
    }                                                                          \
    __syncthreads(); }

__global__ void __launch_bounds__(NT, 1)
mm_kernel(const float* __restrict__ sig, const float* __restrict__ Bext,
          const float* __restrict__ MsatP, const int* __restrict__ srcP,
          const int* __restrict__ probeP, const int* __restrict__ finalP,
          float* __restrict__ out)
{
    extern __shared__ float4 smf4[];

    const int tid   = threadIdx.x;
    const int c     = tid & 255;
    const int ty    = tid >> 8;
    const int r     = blockIdx.x;
    const int lbase = 5 * ty;              // strip start (window row)
    const int kown  = ty ? 0 : 4;          // owned row's k (window row 4/5)
    const int bndL  = ty ? 4 : 5;          // cross-strip boundary row
    const int gown  = 2 * r + ty;          // owned global row

    // Neighbor flag offsets (clamped at domain edges; clamped entries are
    // trivially satisfied since all flags advance uniformly).
    const int fn0 = 8 * (r - 2 < 0 ? 0 : r - 2);
    const int fn1 = 8 * (r - 1 < 0 ? 0 : r - 1);
    const int fn2 = 8 * (r + 1 > NBLK - 1 ? NBLK - 1 : r + 1);
    const int fn3 = 8 * (r + 2 > NBLK - 1 ? NBLK - 1 : r + 2);
    const unsigned fbase = g_flag[8 * r];  // race-free: only CTA r writes it
    unsigned seq = 0;

    const float Msat = *MsatP;
    const float CEx = (float)(2.0 * 3.5e-12 / ((double)Msat * (5e-8 * 5e-8)));
    const float CD  = (float)(4e-7 * 3.14159265358979323846 * (double)Msat);
    const float hh  = (float)(175950000000.0 * 5e-12);   // GAMMA_LL * DT
    const float h2  = 0.5f * hh;
    const float h6  = hh * (1.0f / 6.0f);
    const int final_board = *finalP;

    // Strip rows map to global grow[k] = clamp(2r - 4 + lbase + k).
    int growr[5];
    #pragma unroll
    for (int k = 0; k < 5; k++) {
        int g = 2 * r - 4 + lbase + k;
        growr[k] = g < 0 ? 0 : (g > NXg - 1 ? NXg - 1 : g);
    }

    // B_ext per strip row -> registers.
    float bxr[5], byr[5], bzr[5];
    #pragma unroll
    for (int k = 0; k < 5; k++) {
        int gi = growr[k] * NYg + c;
        bxr[k] = __ldg(Bext + 0 * PLANE + gi);
        byr[k] = __ldg(Bext + 1 * PLANE + gi);
        bzr[k] = __ldg(Bext + 2 * PLANE + gi);
    }

    // Source-id per strip row.
    int sid[5];
    {
        int s0r = srcP[0], s0c = srcP[1];
        int s1r = srcP[2], s1c = srcP[3];
        int s2r = srcP[4], s2c = srcP[5];
        #pragma unroll
        for (int k = 0; k < 5; k++) {
            int g = growr[k];
            sid[k] = (g == s0r && c == s0c) ? 0 :
                     (g == s1r && c == s1c) ? 1 :
                     (g == s2r && c == s2c) ? 2 : -1;
        }
    }
    // Probe-id at owned cell.
    int pid = -1;
    #pragma unroll
    for (int k = 0; k < NPROBE; k++)
        if (probeP[2 * k] == gown && probeP[2 * k + 1] == c) pid = k;

    float ux[5], uy[5], uz[5];          // stage-input values
    float vx[5], vy[5], vz[5];          // stage-output staging
    float mxr[5], myr[5], mzr[5];       // base m for this step
    float bzadd[5];
    #pragma unroll
    for (int k = 0; k < 5; k++) bzadd[k] = 0.0f;

    // ---- init: m0 = (0,1,0) everywhere (smem only; global written per step)
    #pragma unroll
    for (int k = 0; k < 5; k++) {
        int L = lbase + k;
        mxr[k] = 0.0f; myr[k] = 1.0f; mzr[k] = 0.0f;
        ux[k] = 0.0f; uy[k] = 1.0f; uz[k] = 0.0f;
        vx[k] = 0.0f; vy[k] = 1.0f; vz[k] = 0.0f;
        float4 v = make_float4(0.0f, 1.0f, 0.0f, 0.0f);
        U(0, L)[c + 1] = v;
        if (c == 0)   U(0, L)[0]   = v;
        if (c == 255) U(0, L)[257] = v;
    }
    __syncthreads();

    // ---- relax phase: alpha = 0.5 ----
    {
        const float alpha = 0.5f;
        const float inv = 1.0f / (1.0f + alpha * alpha);
        for (int s = 0; s < RELAXN; s++) {
            RK4STEP();
            __stcg(&g_mbuf[(seq + 1) & 1][gown * NYg + c],
                   make_float4(mxr[kown], myr[kown], mzr[kown], 0.0f));
            NBRSYNC();
            RELOAD(g_mbuf[seq & 1]);
        }
    }
    const float mrx = mxr[kown], mry = myr[kown], mrz = mzr[kown];

    // ---- driven phase: alpha = 0.01 ----
    {
        const float alpha = 0.01f;
        const float inv = 1.0f / (1.0f + alpha * alpha);
        for (int sgn = 0; sgn < NSIG; sgn++) {
            if (sgn > 0) {   // reset to m_relaxed (a publish event)
                mxr[kown] = mrx; myr[kown] = mry; mzr[kown] = mrz;
                __stcg(&g_mbuf[(seq + 1) & 1][gown * NYg + c],
                       make_float4(mrx, mry, mrz, 0.0f));
                NBRSYNC();
                RELOAD(g_mbuf[seq & 1]);
            }
            for (int t = 0; t < TSTEPS; t++) {
                const float* sp = sig + (sgn * TSTEPS + t) * NSRC;
                float sv0 = __ldg(sp + 0), sv1 = __ldg(sp + 1), sv2 = __ldg(sp + 2);
                #pragma unroll
                for (int k = 0; k < 5; k++)
                    bzadd[k] = (sid[k] == 0) ? sv0 :
                               (sid[k] == 1) ? sv1 :
                               (sid[k] == 2) ? sv2 : 0.0f;
                RK4STEP();
                __stcg(&g_mbuf[(seq + 1) & 1][gown * NYg + c],
                       make_float4(mxr[kown], myr[kown], mzr[kown], 0.0f));
                if (pid >= 0) {
                    float val = final_board ? (mzr[kown] - mrz) * Msat
                                            : mzr[kown];
                    out[(sgn * TSTEPS + t) * NPROBE + pid] = val;
                }
                NBRSYNC();
                RELOAD(g_mbuf[seq & 1]);
            }
        }
    }
}

extern "C" void kernel_launch(void* const* d_in, const int* in_sizes, int n_in,
                              void* d_out, int out_size) {
    const float* sig    = (const float*)d_in[0];  // (2, 256, 3)
    const float* Bext   = (const float*)d_in[1];  // (1, 3, 256, 256)
    const float* MsatP  = (const float*)d_in[2];  // scalar
    const int*   srcP   = (const int*)d_in[3];    // (3, 2)
    const int*   probeP = (const int*)d_in[4];    // (5, 2)
    const int*   finalP = (const int*)d_in[5];    // scalar
    float* out = (float*)d_out;                   // (2, 256, 5)
    (void)in_sizes; (void)n_in; (void)out_size;

    cudaFuncSetAttribute(mm_kernel,
                         cudaFuncAttributeMaxDynamicSharedMemorySize,
                         SMEM_BYTES);
    mm_kernel<<<NBLK, NT, SMEM_BYTES>>>(sig, Bext, MsatP, srcP, probeP,
                                        finalP, out);
}